// round 6
// baseline (speedup 1.0000x reference)
#include <cuda_runtime.h>
#include <cstdint>

#define En 4096
#define Bn 8
#define HEADS 32
#define Dh 128
#define CK 128               // k-floats per chunk (= one head span)
#define RB 16                // W rows per block
#define SN 4                 // pipeline stages
#define KS 2                 // k-splits
#define KCH (En / (CK * KS)) // 16 chunks per block
#define QKV_BLOCKS 1536      // 3 proj * 256 rowblocks * 2 ksplit
#define OPJ_BLOCKS 512

typedef unsigned long long u64;

__device__ __align__(16) float g_qkv[3 * Bn * En];
__device__ int g_qkv_done;

struct Smem {
    float w[SN][RB][CK];   // 32KB
    float x[SN][Bn][CK];   // 16KB
    float c1[Bn][KCH];     // 512B
    float c2[Bn][KCH];     // 512B
};                         // 49KB -> dynamic smem

__device__ __forceinline__ void fma2(u64 &d, u64 a, u64 b) {
    asm("fma.rn.f32x2 %0, %1, %2, %0;" : "+l"(d) : "l"(a), "l"(b));
}
__device__ __forceinline__ u64 fma2r(u64 a, u64 b, u64 c) {
    u64 d; asm("fma.rn.f32x2 %0, %1, %2, %3;" : "=l"(d) : "l"(a), "l"(b), "l"(c)); return d;
}
__device__ __forceinline__ u64 pack2s(float v) {
    u64 d; asm("mov.b64 %0, {%1, %1};" : "=l"(d) : "f"(v)); return d;
}
__device__ __forceinline__ float2 unpack2(u64 v) {
    float2 r; asm("mov.b64 {%0,%1}, %2;" : "=f"(r.x), "=f"(r.y) : "l"(v)); return r;
}
__device__ __forceinline__ void cp16(uint32_t saddr, const float* g) {
    asm volatile("cp.async.cg.shared.global [%0], [%1], 16;" :: "r"(saddr), "l"(g));
}
__device__ __forceinline__ int ld_acq(const int* p) {
    int v; asm volatile("ld.acquire.gpu.s32 %0, [%1];" : "=r"(v) : "l"(p) : "memory"); return v;
}

// epilogue: butterfly transpose-reduce of 32 per-thread partials, atomicAdd out
__device__ __forceinline__ void reduce_store(u64* acc, float* __restrict__ out,
                                             int row0, int warp, int lane) {
    float vals[32];
#pragma unroll
    for (int i = 0; i < 32; ++i) {
        float2 p = unpack2(acc[i]);
        vals[i] = p.x + p.y;
    }
    int n = 32;
#pragma unroll
    for (int m = 1; m <= 16; m <<= 1) {
        n >>= 1;
        bool up = (lane & m) != 0;
#pragma unroll
        for (int i = 0; i < n; ++i) {
            float keep = up ? vals[i + n] : vals[i];
            float send = up ? vals[i] : vals[i + n];
            keep += __shfl_xor_sync(0xffffffffu, send, m);
            vals[i] = keep;
        }
    }
    int j = ((lane & 1) << 4) | ((lane & 2) << 2) | (lane & 4) |
            ((lane >> 2) & 2) | ((lane >> 4) & 1);
    int r = j >> 3;
    int b = j & 7;
    atomicAdd(&out[(size_t)b * En + row0 + warp * 4 + r], vals[0]);
}

// ---------------- qkv role ----------------
__device__ __forceinline__ void qkv_work(const float* __restrict__ W,
                                         const float* __restrict__ X,
                                         float* __restrict__ out,
                                         int row0, int k0, Smem& sm) {
    const int t = threadIdx.x, warp = t >> 5, lane = t & 31;
    uint32_t swb = (uint32_t)__cvta_generic_to_shared(&sm.w[0][0][0]);
    uint32_t sxb = (uint32_t)__cvta_generic_to_shared(&sm.x[0][0][0]);

    const float* wg[4]; uint32_t wsm[4];
#pragma unroll
    for (int p = 0; p < 4; ++p) {
        int u = p * 128 + t, r = u >> 5, c = u & 31;
        wg[p] = W + (size_t)(row0 + r) * En + k0 + c * 4;
        wsm[p] = swb + u * 16;
    }
    const float* xg[2]; uint32_t xsm[2];
#pragma unroll
    for (int p = 0; p < 2; ++p) {
        int u = p * 128 + t, b = u >> 5, c = u & 31;
        xg[p] = X + (size_t)b * En + k0 + c * 4;
        xsm[p] = sxb + u * 16;
    }

    auto issue_stage = [&](int st, int kc) {
        int koff = kc * CK;
        uint32_t wo = st * (RB * CK * 4);
        uint32_t xo = st * (Bn * CK * 4);
#pragma unroll
        for (int p = 0; p < 4; ++p) cp16(wsm[p] + wo, wg[p] + koff);
#pragma unroll
        for (int p = 0; p < 2; ++p) cp16(xsm[p] + xo, xg[p] + koff);
        asm volatile("cp.async.commit_group;");
    };

#pragma unroll
    for (int s = 0; s < SN - 1; ++s) issue_stage(s, s);

    u64 acc[32];
#pragma unroll
    for (int i = 0; i < 32; ++i) acc[i] = 0ull;

    for (int i = 0; i < KCH; ++i) {
        asm volatile("cp.async.wait_group %0;" :: "n"(SN - 2));
        __syncthreads();
        int nk = i + SN - 1;
        if (nk < KCH) issue_stage(nk % SN, nk);
        else asm volatile("cp.async.commit_group;");

        int st = i % SN;
        longlong2 wv[4];
#pragma unroll
        for (int r = 0; r < 4; ++r)
            wv[r] = *reinterpret_cast<const longlong2*>(&sm.w[st][warp * 4 + r][lane * 4]);
#pragma unroll
        for (int b = 0; b < 8; ++b) {
            longlong2 xv = *reinterpret_cast<const longlong2*>(&sm.x[st][b][lane * 4]);
#pragma unroll
            for (int r = 0; r < 4; ++r) {
                fma2(acc[r * 8 + b], (u64)wv[r].x, (u64)xv.x);
                fma2(acc[r * 8 + b], (u64)wv[r].y, (u64)xv.y);
            }
        }
    }
    reduce_store(acc, out, row0, warp, lane);
}

// ---------------- oproj role ----------------
__device__ __forceinline__ void opj_work(const float* __restrict__ W,
                                         float* __restrict__ out,
                                         int row0, int k0, Smem& sm) {
    const int t = threadIdx.x, warp = t >> 5, lane = t & 31;
    const float* V = g_qkv + 2 * Bn * En;
    uint32_t swb = (uint32_t)__cvta_generic_to_shared(&sm.w[0][0][0]);
    uint32_t sxb = (uint32_t)__cvta_generic_to_shared(&sm.x[0][0][0]);

    const float* wg[4]; uint32_t wsm[4];
#pragma unroll
    for (int p = 0; p < 4; ++p) {
        int u = p * 128 + t, r = u >> 5, c = u & 31;
        wg[p] = W + (size_t)(row0 + r) * En + k0 + c * 4;
        wsm[p] = swb + u * 16;
    }
    const float* xg[2]; uint32_t xsm[2];
#pragma unroll
    for (int p = 0; p < 2; ++p) {
        int u = p * 128 + t, b = u >> 5, c = u & 31;
        xg[p] = V + (size_t)b * En + k0 + c * 4;
        xsm[p] = sxb + u * 16;
    }

    auto issue_w = [&](int st, int kc) {
        int koff = kc * CK;
        uint32_t wo = st * (RB * CK * 4);
#pragma unroll
        for (int p = 0; p < 4; ++p) cp16(wsm[p] + wo, wg[p] + koff);
        asm volatile("cp.async.commit_group;");
    };
    auto issue_x = [&](int st, int kc) {
        int koff = kc * CK;
        uint32_t xo = st * (Bn * CK * 4);
#pragma unroll
        for (int p = 0; p < 2; ++p) cp16(xsm[p] + xo, xg[p] + koff);
        asm volatile("cp.async.commit_group;");
    };
    auto issue_wx = [&](int st, int kc) {
        int koff = kc * CK;
        uint32_t wo = st * (RB * CK * 4);
        uint32_t xo = st * (Bn * CK * 4);
#pragma unroll
        for (int p = 0; p < 4; ++p) cp16(wsm[p] + wo, wg[p] + koff);
#pragma unroll
        for (int p = 0; p < 2; ++p) cp16(xsm[p] + xo, xg[p] + koff);
        asm volatile("cp.async.commit_group;");
    };

    // Prefetch Wo stages while qkv still running (no dependency).
    #pragma unroll
    for (int s = 0; s < SN - 1; ++s) issue_w(s, s);

    // Wait for all qkv partials (v, q, k complete after counter hits target).
    if (t == 0) {
        while (ld_acq(&g_qkv_done) < QKV_BLOCKS) __nanosleep(128);
    }
    __syncthreads();

    // Per-block attention coefficients for its 16 heads x 8 batches.
    int h0 = k0 / Dh;
    const float scale = 0.08838834764831845f;  // 1/sqrt(128)
    for (int i = warp; i < Bn * KCH; i += 4) {
        int b = i >> 4, hl = i & 15;
        const float4* q4 = reinterpret_cast<const float4*>(g_qkv + (size_t)(0 * Bn + b) * En + (h0 + hl) * Dh);
        const float4* k4 = reinterpret_cast<const float4*>(g_qkv + (size_t)(1 * Bn + b) * En + (h0 + hl) * Dh);
        float4 qv = q4[lane];
        float4 kv = k4[lane];
        float sq = qv.x + qv.y + qv.z + qv.w;
        float dp = qv.x * kv.x + qv.y * kv.y + qv.z * kv.z + qv.w * kv.w;
#pragma unroll
        for (int m = 16; m >= 1; m >>= 1) {
            sq += __shfl_xor_sync(0xffffffffu, sq, m);
            dp += __shfl_xor_sync(0xffffffffu, dp, m);
        }
        if (lane == 0) {
            float s0 = sq * scale, sL = dp * scale;
            float mx = fmaxf(s0, sL);
            float e0 = expf(s0 - mx), eL = expf(sL - mx);
            float inv = 1.0f / (4095.0f * e0 + eL);
            sm.c1[b][hl] = 4095.0f * e0 * inv;
            sm.c2[b][hl] = eL * inv;
        }
    }

    // Now v is safe to stream.
    #pragma unroll
    for (int s = 0; s < SN - 1; ++s) issue_x(s, s);
    __syncthreads();  // c table visible

    u64 acc[32];
#pragma unroll
    for (int i = 0; i < 32; ++i) acc[i] = 0ull;

    for (int i = 0; i < KCH; ++i) {
        asm volatile("cp.async.wait_group %0;" :: "n"(SN - 2));
        __syncthreads();
        int nk = i + SN - 1;
        if (nk < KCH) issue_wx(nk % SN, nk);
        else asm volatile("cp.async.commit_group;");

        int st = i % SN;
        longlong2 wv[4];
#pragma unroll
        for (int r = 0; r < 4; ++r)
            wv[r] = *reinterpret_cast<const longlong2*>(&sm.w[st][warp * 4 + r][lane * 4]);
#pragma unroll
        for (int b = 0; b < 8; ++b) {
            longlong2 vv = *reinterpret_cast<const longlong2*>(&sm.x[st][b][lane * 4]);
            u64 c1p = pack2s(sm.c1[b][i]);
            u64 c2p = pack2s(sm.c2[b][i]);
            u64 o0 = fma2r((u64)vv.x, c2p, c1p);   // o = c1 + c2*v
            u64 o1 = fma2r((u64)vv.y, c2p, c1p);
#pragma unroll
            for (int r = 0; r < 4; ++r) {
                fma2(acc[r * 8 + b], (u64)wv[r].x, o0);
                fma2(acc[r * 8 + b], (u64)wv[r].y, o1);
            }
        }
    }
    reduce_store(acc, out, row0, warp, lane);
}

// ---------------- kernels ----------------
__global__ void __launch_bounds__(256)
init_kernel(float* __restrict__ out) {
    int i = blockIdx.x * 256 + threadIdx.x;  // 8192 threads
    float4 z = make_float4(0.f, 0.f, 0.f, 0.f);
    float4* q4 = reinterpret_cast<float4*>(g_qkv);
#pragma unroll
    for (int p = 0; p < 3; ++p) q4[p * 8192 + i] = z;
    reinterpret_cast<float4*>(out)[i] = z;
    if (i == 0) g_qkv_done = 0;
}

__global__ void __launch_bounds__(128, 4)
fused_kernel(const float* __restrict__ Wq, const float* __restrict__ Wk,
             const float* __restrict__ Wv, const float* __restrict__ Wo,
             const float* __restrict__ x, float* __restrict__ out) {
    extern __shared__ char smem_raw[];
    Smem& sm = *reinterpret_cast<Smem*>(smem_raw);
    int bid = blockIdx.x;

    if (bid < QKV_BLOCKS) {
        int p = bid >> 9;          // 512 blocks per projection
        int rem = bid & 511;
        int rb = rem >> 1, ks = rem & 1;
        const float* W = (p == 0) ? Wq : ((p == 1) ? Wk : Wv);
        qkv_work(W, x, g_qkv + (size_t)p * Bn * En, rb * RB, ks * (En / KS), sm);
        __syncthreads();
        __threadfence();
        if (threadIdx.x == 0) atomicAdd(&g_qkv_done, 1);
    } else {
        int rem = bid - QKV_BLOCKS;
        int rb = rem >> 1, ks = rem & 1;
        opj_work(Wo, out, rb * RB, ks * (En / KS), sm);
    }
}

extern "C" void kernel_launch(void* const* d_in, const int* in_sizes, int n_in,
                              void* d_out, int out_size) {
    const float* x  = (const float*)d_in[0];
    const float* Wq = (const float*)d_in[1];
    const float* Wk = (const float*)d_in[2];
    const float* Wv = (const float*)d_in[3];
    const float* Wo = (const float*)d_in[4];
    float* out = (float*)d_out;

    static int smem_set = 0;
    if (!smem_set) {
        cudaFuncSetAttribute(fused_kernel, cudaFuncAttributeMaxDynamicSharedMemorySize,
                             (int)sizeof(Smem));
        smem_set = 1;
    }

    init_kernel<<<32, 256>>>(out);
    fused_kernel<<<QKV_BLOCKS + OPJ_BLOCKS, 128, sizeof(Smem)>>>(Wq, Wk, Wv, Wo, x, out);
}

// round 7
// speedup vs baseline: 1.3749x; 1.3749x over previous
#include <cuda_runtime.h>
#include <cstdint>

#define En 4096
#define Bn 8
#define HEADS 32
#define Dh 128
#define CK 128               // k-floats per chunk
#define RB 16                // W rows per block
#define SN 4                 // pipeline stages
#define KS 4                 // k-splits per output row
#define KCH (En / (CK * KS)) // 8 chunks per block

typedef unsigned long long u64;

__device__ __align__(16) float g_qkv[3 * Bn * En];
__device__ __align__(16) float g_o[Bn * En];

__device__ __forceinline__ void fma2(u64 &d, u64 a, u64 b) {
    asm("fma.rn.f32x2 %0, %1, %2, %0;" : "+l"(d) : "l"(a), "l"(b));
}
__device__ __forceinline__ float2 unpack2(u64 v) {
    float2 r; asm("mov.b64 {%0,%1}, %2;" : "=f"(r.x), "=f"(r.y) : "l"(v)); return r;
}
__device__ __forceinline__ void cp16(uint32_t saddr, const float* g) {
    asm volatile("cp.async.cg.shared.global [%0], [%1], 16;" :: "r"(saddr), "l"(g));
}

struct SmemTiles {
    float w[SN][RB][CK];  // 4 x 8KB
    float x[SN][Bn][CK];  // 4 x 4KB
};                        // 48KB

// Block (128 thr, 4 warps): 16 rows x 8 batches over k-range [k0, k0+1024),
// partial sums atomicAdd'ed into out (zero-initialized upfront).
__device__ __forceinline__ void gemm_block(const float* __restrict__ W,
                                           const float* __restrict__ X,
                                           float* __restrict__ out,
                                           int row0, int k0) {
    __shared__ SmemTiles sm;
    const int t = threadIdx.x;
    const int warp = t >> 5, lane = t & 31;

    uint32_t swb = (uint32_t)__cvta_generic_to_shared(&sm.w[0][0][0]);
    uint32_t sxb = (uint32_t)__cvta_generic_to_shared(&sm.x[0][0][0]);

    const float* wg[4]; uint32_t wsm[4];
#pragma unroll
    for (int p = 0; p < 4; ++p) {
        int u = p * 128 + t, r = u >> 5, c = u & 31;
        wg[p] = W + (size_t)(row0 + r) * En + k0 + c * 4;
        wsm[p] = swb + u * 16;
    }
    const float* xg[2]; uint32_t xsm[2];
#pragma unroll
    for (int p = 0; p < 2; ++p) {
        int u = p * 128 + t, b = u >> 5, c = u & 31;
        xg[p] = X + (size_t)b * En + k0 + c * 4;
        xsm[p] = sxb + u * 16;
    }

    auto issue_stage = [&](int st, int kc) {
        int koff = kc * CK;
        uint32_t wo = st * (RB * CK * 4);
        uint32_t xo = st * (Bn * CK * 4);
#pragma unroll
        for (int p = 0; p < 4; ++p) cp16(wsm[p] + wo, wg[p] + koff);
#pragma unroll
        for (int p = 0; p < 2; ++p) cp16(xsm[p] + xo, xg[p] + koff);
        asm volatile("cp.async.commit_group;");
    };

#pragma unroll
    for (int s = 0; s < SN - 1; ++s) issue_stage(s, s);

    u64 acc[32];  // [r(4)][b(8)] packed (even-k, odd-k)
#pragma unroll
    for (int i = 0; i < 32; ++i) acc[i] = 0ull;

    for (int i = 0; i < KCH; ++i) {
        asm volatile("cp.async.wait_group %0;" :: "n"(SN - 2));
        __syncthreads();

        int nk = i + SN - 1;
        if (nk < KCH) issue_stage(nk % SN, nk);
        else asm volatile("cp.async.commit_group;");

        int st = i % SN;
        longlong2 wv[4];
#pragma unroll
        for (int r = 0; r < 4; ++r)
            wv[r] = *reinterpret_cast<const longlong2*>(&sm.w[st][warp * 4 + r][lane * 4]);
#pragma unroll
        for (int b = 0; b < 8; ++b) {
            longlong2 xv = *reinterpret_cast<const longlong2*>(&sm.x[st][b][lane * 4]);
#pragma unroll
            for (int r = 0; r < 4; ++r) {
                fma2(acc[r * 8 + b], (u64)wv[r].x, (u64)xv.x);
                fma2(acc[r * 8 + b], (u64)wv[r].y, (u64)xv.y);
            }
        }
    }

    float vals[32];
#pragma unroll
    for (int i = 0; i < 32; ++i) {
        float2 p = unpack2(acc[i]);
        vals[i] = p.x + p.y;
    }

    // butterfly transpose-reduce: lane L ends with value index bitrev5(L)
    int n = 32;
#pragma unroll
    for (int m = 1; m <= 16; m <<= 1) {
        n >>= 1;
        bool up = (lane & m) != 0;
#pragma unroll
        for (int i = 0; i < n; ++i) {
            float keep = up ? vals[i + n] : vals[i];
            float send = up ? vals[i] : vals[i + n];
            keep += __shfl_xor_sync(0xffffffffu, send, m);
            vals[i] = keep;
        }
    }
    int j = ((lane & 1) << 4) | ((lane & 2) << 2) | (lane & 4) |
            ((lane >> 2) & 2) | ((lane >> 4) & 1);
    int r = j >> 3;
    int b = j & 7;
    atomicAdd(&out[(size_t)b * En + row0 + warp * 4 + r], vals[0]);
}

// zero g_qkv only (24576 float4 over 8192 threads)
__global__ void __launch_bounds__(256)
init_kernel() {
    int i = blockIdx.x * 256 + threadIdx.x;  // 8192 threads
    float4 z = make_float4(0.f, 0.f, 0.f, 0.f);
    float4* q4 = reinterpret_cast<float4*>(g_qkv);
#pragma unroll
    for (int p = 0; p < 3; ++p) q4[p * 8192 + i] = z;
}

// grid (1024, 3): blockIdx.x = rowblock*4 + ksplit; blockIdx.y = projection
__global__ void __launch_bounds__(128, 4)
qkv_kernel(const float* __restrict__ Wq, const float* __restrict__ Wk,
           const float* __restrict__ Wv, const float* __restrict__ x) {
    int rb = blockIdx.x >> 2, ks = blockIdx.x & 3;
    const float* W = (blockIdx.y == 0) ? Wq : ((blockIdx.y == 1) ? Wk : Wv);
    gemm_block(W, x, g_qkv + blockIdx.y * (Bn * En), rb * RB, ks * (En / KS));
}

// Attention with all-ones KV cache collapses to o[d] = c1 + c2 * v[d] per (b,h).
// Also zero-initializes d_out for oproj's atomic accumulation.
__global__ void __launch_bounds__(256)
attn_kernel(float* __restrict__ out) {
    int gtid = blockIdx.x * blockDim.x + threadIdx.x;
    reinterpret_cast<float4*>(out)[gtid] = make_float4(0.f, 0.f, 0.f, 0.f);

    int warp = gtid >> 5;
    int lane = gtid & 31;
    int b = warp >> 5;
    int h = warp & 31;

    const float4* q4 = reinterpret_cast<const float4*>(g_qkv + (0 * Bn + b) * En + h * Dh);
    const float4* k4 = reinterpret_cast<const float4*>(g_qkv + (1 * Bn + b) * En + h * Dh);
    const float4* v4 = reinterpret_cast<const float4*>(g_qkv + (2 * Bn + b) * En + h * Dh);

    float4 qv = q4[lane];
    float4 kv = k4[lane];
    float4 vv = v4[lane];

    float sq = qv.x + qv.y + qv.z + qv.w;
    float dp = qv.x * kv.x + qv.y * kv.y + qv.z * kv.z + qv.w * kv.w;
#pragma unroll
    for (int m = 16; m >= 1; m >>= 1) {
        sq += __shfl_xor_sync(0xffffffffu, sq, m);
        dp += __shfl_xor_sync(0xffffffffu, dp, m);
    }

    const float scale = 0.08838834764831845f;  // 1/sqrt(128)
    float s0 = sq * scale;
    float sL = dp * scale;
    float mx = fmaxf(s0, sL);
    float e0 = expf(s0 - mx);
    float eL = expf(sL - mx);
    float inv = 1.0f / (4095.0f * e0 + eL);
    float c1 = 4095.0f * e0 * inv;
    float c2 = eL * inv;

    float4* o4 = reinterpret_cast<float4*>(g_o + b * En + h * Dh);
    o4[lane] = make_float4(c1 + c2 * vv.x, c1 + c2 * vv.y,
                           c1 + c2 * vv.z, c1 + c2 * vv.w);
}

// grid 1024: blockIdx.x = rowblock*4 + ksplit
__global__ void __launch_bounds__(128, 4)
oproj_kernel(const float* __restrict__ Wo, float* __restrict__ out) {
    int rb = blockIdx.x >> 2, ks = blockIdx.x & 3;
    gemm_block(Wo, g_o, out, rb * RB, ks * (En / KS));
}

extern "C" void kernel_launch(void* const* d_in, const int* in_sizes, int n_in,
                              void* d_out, int out_size) {
    const float* x  = (const float*)d_in[0];
    const float* Wq = (const float*)d_in[1];
    const float* Wk = (const float*)d_in[2];
    const float* Wv = (const float*)d_in[3];
    const float* Wo = (const float*)d_in[4];
    float* out = (float*)d_out;

    init_kernel<<<32, 256>>>();
    dim3 gq(1024, 3);
    qkv_kernel<<<gq, 128>>>(Wq, Wk, Wv, x);
    attn_kernel<<<32, 256>>>(out);
    oproj_kernel<<<1024, 128>>>(Wo, out);
}